// round 15
// baseline (speedup 1.0000x reference)
#include <cuda_runtime.h>

#define BB 4
#define TT_TOT 1024
#define HW 1296
#define NBINS 512
#define LOOKUP 101
#define OUT_DIM 128

// band kernel (tf32 mma)
#define BTILE 16
#define BROWS 128          // j in [tb-56, tb+72)
#define SSTRIDE 68         // floats per smem row (64 + 4 pad -> conflict-free frags)
#define KCH 64             // K per stage
#define NSTAGES 8          // 512 / 64
#define STAGE_WORDS (BROWS * SSTRIDE)        // 8704
// fused fc smem layout: UNION with stage buffers (used only after MMA loop)
#define SW_OFF   0                            // W: 101*128 = 12928
#define SB_OFF   (LOOKUP * OUT_DIM)           // bias: 128
#define SWIN_OFF (SB_OFF + OUT_DIM)           // win: 16*104 = 1664 (ends 14720)
#define WINP 104
#define SMEM_FLOATS (2 * STAGE_WORDS)         // 17408 floats = 69632 B

__device__ float g_hist[BB * TT_TOT * NBINS];   // 8 MB tf32-rounded normalized hists

// ---------------------------------------------------------------------------
// Kernel 1: per-frame 512-bin color histogram + L2 normalize (tf32-rounded).
// ---------------------------------------------------------------------------
__global__ void hist_kernel(const int* __restrict__ frames, int fbase) {
    __shared__ int hists[4 * 520];   // 4 copies, 520-int stride
    __shared__ float wsum[8];
    const int f = fbase + blockIdx.x;
    const int tid = threadIdx.x;     // 256

    for (int i = tid; i < 4 * 520; i += 256) hists[i] = 0;
    __syncthreads();

    const int4* p = (const int4*)frames + (size_t)f * (HW * 3 / 4);
    int* myh = hists + (tid & 3) * 520;

    for (int q = tid; q < HW / 4; q += 256) {
        int4 a = p[3 * q + 0];
        int4 b = p[3 * q + 1];
        int4 c = p[3 * q + 2];
        int b0 = ((a.x >> 5) << 6) | ((a.y >> 5) << 3) | (a.z >> 5);
        int b1 = ((a.w >> 5) << 6) | ((b.x >> 5) << 3) | (b.y >> 5);
        int b2 = ((b.z >> 5) << 6) | ((b.w >> 5) << 3) | (c.x >> 5);
        int b3 = ((c.y >> 5) << 6) | ((c.z >> 5) << 3) | (c.w >> 5);
        atomicAdd(&myh[b0], 1);
        atomicAdd(&myh[b1], 1);
        atomicAdd(&myh[b2], 1);
        atomicAdd(&myh[b3], 1);
    }
    __syncthreads();

    float h0 = (float)(hists[tid] + hists[520 + tid] + hists[1040 + tid] + hists[1560 + tid]);
    float h1 = (float)(hists[tid + 256] + hists[520 + tid + 256] +
                       hists[1040 + tid + 256] + hists[1560 + tid + 256]);
    float s = h0 * h0 + h1 * h1;
#pragma unroll
    for (int o = 16; o > 0; o >>= 1) s += __shfl_xor_sync(0xffffffffu, s, o);
    if ((tid & 31) == 0) wsum[tid >> 5] = s;
    __syncthreads();

    float tot = 0.f;
#pragma unroll
    for (int w = 0; w < 8; w++) tot += wsum[w];
    float rn = rsqrtf(tot);   // tot >= HW^2/NBINS > 0

    unsigned u0, u1;
    asm("cvt.rna.tf32.f32 %0, %1;" : "=r"(u0) : "f"(h0 * rn));
    asm("cvt.rna.tf32.f32 %0, %1;" : "=r"(u1) : "f"(h1 * rn));
    float* o = g_hist + (size_t)f * NBINS;
    o[tid] = __uint_as_float(u0);
    o[tid + 256] = __uint_as_float(u1);
}

// ---------------------------------------------------------------------------
// Kernel 2: banded self-similarity via tf32 mma.sync (m16n8k8) + fused FC.
// Block = one 16-t tile of one batch; dense D[16 x 128] over K=512.
// 8 warps: all share the m16 tile; warp w covers n columns [16w, 16w+16).
// smem: 2 stage buffers (double-buffered cp.async); FC W/bias/window UNION
// into the stage region after the MMA loop completes.
// ---------------------------------------------------------------------------
__global__ void band_kernel(const float* __restrict__ fcw,
                            const float* __restrict__ fcb,
                            float* __restrict__ out, int b) {
    extern __shared__ __align__(16) float sm[];   // SMEM_FLOATS

    const int tb = blockIdx.x * BTILE;        // 0..1008
    const int j0 = tb - 56;
    const int tid = threadIdx.x;              // 256
    const int lane = tid & 31, warp = tid >> 5;

    const float* hb = g_hist + (size_t)b * (TT_TOT * NBINS);

    float acc[2][4];
#pragma unroll
    for (int nt = 0; nt < 2; nt++)
#pragma unroll
        for (int i = 0; i < 4; i++) acc[nt][i] = 0.f;

    // ---- stage loader: 128 rows x 16 float4 = 2048 cp.asyncs, 8 per thread.
    const int lrow0 = tid >> 4;
    const int lc4 = tid & 15;
    unsigned sbase = (unsigned)__cvta_generic_to_shared(sm);

    const float* lsrc[8];
    int lsz[8];
    unsigned ldst[8];
#pragma unroll
    for (int it = 0; it < 8; ++it) {
        int row = lrow0 + it * 16;
        int j = j0 + row;
        int jc = j < 0 ? 0 : (j > 1023 ? 1023 : j);
        lsrc[it] = hb + (size_t)jc * NBINS + lc4 * 4;
        lsz[it] = ((unsigned)j < 1024u) ? 16 : 0;
        ldst[it] = sbase + (unsigned)(row * SSTRIDE + lc4 * 4) * 4u;
    }

#define LOAD_STAGE(s, buf)                                                        \
    {                                                                             \
        const int kb = (s) * KCH;                                                 \
        const unsigned boff = (buf) * (STAGE_WORDS * 4u);                         \
        _Pragma("unroll")                                                         \
        for (int it = 0; it < 8; ++it) {                                          \
            asm volatile("cp.async.cg.shared.global [%0], [%1], 16, %2;\n"        \
                         :: "r"(ldst[it] + boff), "l"(lsrc[it] + kb),             \
                            "r"(lsz[it]));                                        \
        }                                                                         \
        asm volatile("cp.async.commit_group;\n");                                 \
    }

    LOAD_STAGE(0, 0)

    for (int s = 0; s < NSTAGES; ++s) {
        if (s < NSTAGES - 1) LOAD_STAGE(s + 1, (s + 1) & 1)
        asm volatile("cp.async.wait_group 1;\n" ::: "memory");
        __syncthreads();

        const float* B = sm + (s & 1) * STAGE_WORDS;
        const float* Ab = B + (56 + (lane >> 2)) * SSTRIDE + (lane & 3);
        const float* Bb = B + (warp * 16 + (lane >> 2)) * SSTRIDE + (lane & 3);

#pragma unroll
        for (int k8 = 0; k8 < KCH / 8; ++k8) {
            const int ko = k8 * 8;
            unsigned a0 = __float_as_uint(Ab[ko]);
            unsigned a1 = __float_as_uint(Ab[8 * SSTRIDE + ko]);
            unsigned a2 = __float_as_uint(Ab[ko + 4]);
            unsigned a3 = __float_as_uint(Ab[8 * SSTRIDE + ko + 4]);
#pragma unroll
            for (int nt = 0; nt < 2; ++nt) {
                unsigned b0 = __float_as_uint(Bb[nt * 8 * SSTRIDE + ko]);
                unsigned b1 = __float_as_uint(Bb[nt * 8 * SSTRIDE + ko + 4]);
                asm volatile(
                    "mma.sync.aligned.m16n8k8.row.col.f32.tf32.tf32.f32 "
                    "{%0,%1,%2,%3}, {%4,%5,%6,%7}, {%8,%9}, {%0,%1,%2,%3};\n"
                    : "+f"(acc[nt][0]), "+f"(acc[nt][1]),
                      "+f"(acc[nt][2]), "+f"(acc[nt][3])
                    : "r"(a0), "r"(a1), "r"(a2), "r"(a3), "r"(b0), "r"(b1));
            }
        }
        __syncthreads();
    }
    // All stage-buffer reads done; smem region is now reused for FC data.

    // ---- epilogue 1: scatter D(tr, jr) -> swin[tr][l], l = jr - tr - 6.
    {
        float* swin = sm + SWIN_OFF;
        const int tr0 = lane >> 2;
#pragma unroll
        for (int nt = 0; nt < 2; ++nt) {
            int jr = warp * 16 + nt * 8 + 2 * (lane & 3);
#pragma unroll
            for (int half = 0; half < 2; ++half) {
                int tr = tr0 + half * 8;
                int l = jr - tr - 6;
                if ((unsigned)l < (unsigned)LOOKUP)
                    swin[tr * WINP + l] = acc[nt][2 * half];
                if ((unsigned)(l + 1) < (unsigned)LOOKUP)
                    swin[tr * WINP + l + 1] = acc[nt][2 * half + 1];
            }
        }
    }

    // stage FC weights/bias into the freed stage region (disjoint from swin)
    {
        const float4* w4 = (const float4*)fcw;
        float4* sw4 = (float4*)(sm + SW_OFF);
        for (int e = tid; e < (LOOKUP * OUT_DIM) / 4; e += 256) sw4[e] = w4[e];
        if (tid < OUT_DIM) sm[SB_OFF + tid] = fcb[tid];
    }
    __syncthreads();

    // ---- epilogue 2: fused FC. Warp w -> t rows {2w, 2w+1}; lane -> 4 cols.
    {
        const float* sW = sm + SW_OFF;
        const float* swin = sm + SWIN_OFF;
        float4 bias = *(const float4*)(sm + SB_OFF + 4 * lane);

        float f[2][4];
#pragma unroll
        for (int r = 0; r < 2; ++r) {
            f[r][0] = bias.x; f[r][1] = bias.y; f[r][2] = bias.z; f[r][3] = bias.w;
        }

#pragma unroll 4
        for (int l = 0; l < LOOKUP; ++l) {
            float4 wv = *(const float4*)(sW + l * OUT_DIM + 4 * lane);
#pragma unroll
            for (int r = 0; r < 2; ++r) {
                float sv = swin[(2 * warp + r) * WINP + l];
                f[r][0] += sv * wv.x;
                f[r][1] += sv * wv.y;
                f[r][2] += sv * wv.z;
                f[r][3] += sv * wv.w;
            }
        }

#pragma unroll
        for (int r = 0; r < 2; ++r) {
            int t = tb + 2 * warp + r;
            float4 o;
            o.x = fmaxf(f[r][0], 0.f);
            o.y = fmaxf(f[r][1], 0.f);
            o.z = fmaxf(f[r][2], 0.f);
            o.w = fmaxf(f[r][3], 0.f);
            *(float4*)(out + ((size_t)(b * TT_TOT + t)) * OUT_DIM + 4 * lane) = o;
        }
    }
}

// ---------------------------------------------------------------------------
// Launch: batch-pipelined. hist(b) on the capture stream; band(b) on a forked
// stream gated by an event recorded after hist(b). The graph executor then
// overlaps band(b) with hist(b+1..). Joined back before return.
// ---------------------------------------------------------------------------
extern "C" void kernel_launch(void* const* d_in, const int* in_sizes, int n_in,
                              void* d_out, int out_size) {
    const int* frames = (const int*)d_in[0];
    const float* fcw = (const float*)d_in[1];
    const float* fcb = (const float*)d_in[2];
    float* out = (float*)d_out;

    cudaFuncSetAttribute(band_kernel, cudaFuncAttributeMaxDynamicSharedMemorySize,
                         SMEM_FLOATS * (int)sizeof(float));

    cudaStream_t s2;
    cudaStreamCreate(&s2);
    cudaEvent_t ev[BB], evj;

    for (int b = 0; b < BB; ++b) {
        hist_kernel<<<TT_TOT, 256>>>(frames, b * TT_TOT);
        cudaEventCreateWithFlags(&ev[b], cudaEventDisableTiming);
        cudaEventRecord(ev[b], 0);
    }
    for (int b = 0; b < BB; ++b) {
        cudaStreamWaitEvent(s2, ev[b], 0);
        band_kernel<<<TT_TOT / BTILE, 256, SMEM_FLOATS * sizeof(float), s2>>>(
            fcw, fcb, out, b);
    }
    cudaEventCreateWithFlags(&evj, cudaEventDisableTiming);
    cudaEventRecord(evj, s2);
    cudaStreamWaitEvent(0, evj, 0);
}

// round 16
// speedup vs baseline: 2.1132x; 2.1132x over previous
#include <cuda_runtime.h>

#define BB 4
#define TT_TOT 1024
#define HW 1296
#define NBINS 512
#define LOOKUP 101
#define OUT_DIM 128

// band kernel (tf32 mma)
#define BTILE 16
#define BROWS 128          // j in [tb-56, tb+72)
#define SSTRIDE 68         // floats per smem row (64 + 4 pad -> conflict-free frags)
#define KCH 64             // K per stage
#define NSTAGES 8          // 512 / 64
#define STAGE_WORDS (BROWS * SSTRIDE)        // 8704
// fused fc smem layout: UNION with stage buffers (used only after MMA loop)
#define SW_OFF   0                            // W: 101*128 = 12928
#define SB_OFF   (LOOKUP * OUT_DIM)           // bias: 128
#define SWIN_OFF (SB_OFF + OUT_DIM)           // win: 16*104 = 1664 (ends 14720)
#define WINP 104
#define SMEM_FLOATS (2 * STAGE_WORDS)         // 17408 floats = 69632 B

__device__ float g_hist[BB * TT_TOT * NBINS];   // 8 MB tf32-rounded normalized hists

// ---------------------------------------------------------------------------
// Kernel 1: per-frame 512-bin color histogram + L2 normalize (tf32-rounded).
// Single 4096-block launch (full-depth wave saturates HBM/ATOMS).
// ---------------------------------------------------------------------------
__global__ void hist_kernel(const int* __restrict__ frames) {
    __shared__ int hists[4 * 520];   // 4 copies, 520-int stride
    __shared__ float wsum[8];
    const int f = blockIdx.x;
    const int tid = threadIdx.x;     // 256

    for (int i = tid; i < 4 * 520; i += 256) hists[i] = 0;
    __syncthreads();

    const int4* p = (const int4*)frames + (size_t)f * (HW * 3 / 4);
    int* myh = hists + (tid & 3) * 520;

    for (int q = tid; q < HW / 4; q += 256) {
        int4 a = p[3 * q + 0];
        int4 b = p[3 * q + 1];
        int4 c = p[3 * q + 2];
        int b0 = ((a.x >> 5) << 6) | ((a.y >> 5) << 3) | (a.z >> 5);
        int b1 = ((a.w >> 5) << 6) | ((b.x >> 5) << 3) | (b.y >> 5);
        int b2 = ((b.z >> 5) << 6) | ((b.w >> 5) << 3) | (c.x >> 5);
        int b3 = ((c.y >> 5) << 6) | ((c.z >> 5) << 3) | (c.w >> 5);
        atomicAdd(&myh[b0], 1);
        atomicAdd(&myh[b1], 1);
        atomicAdd(&myh[b2], 1);
        atomicAdd(&myh[b3], 1);
    }
    __syncthreads();

    float h0 = (float)(hists[tid] + hists[520 + tid] + hists[1040 + tid] + hists[1560 + tid]);
    float h1 = (float)(hists[tid + 256] + hists[520 + tid + 256] +
                       hists[1040 + tid + 256] + hists[1560 + tid + 256]);
    float s = h0 * h0 + h1 * h1;
#pragma unroll
    for (int o = 16; o > 0; o >>= 1) s += __shfl_xor_sync(0xffffffffu, s, o);
    if ((tid & 31) == 0) wsum[tid >> 5] = s;
    __syncthreads();

    float tot = 0.f;
#pragma unroll
    for (int w = 0; w < 8; w++) tot += wsum[w];
    float rn = rsqrtf(tot);   // tot >= HW^2/NBINS > 0

    unsigned u0, u1;
    asm("cvt.rna.tf32.f32 %0, %1;" : "=r"(u0) : "f"(h0 * rn));
    asm("cvt.rna.tf32.f32 %0, %1;" : "=r"(u1) : "f"(h1 * rn));
    float* o = g_hist + (size_t)f * NBINS;
    o[tid] = __uint_as_float(u0);
    o[tid + 256] = __uint_as_float(u1);
}

// ---------------------------------------------------------------------------
// Kernel 2: banded self-similarity via tf32 mma.sync (m16n8k8) + fused FC.
// Block = one 16-t tile; dense D[16 x 128] over K=512, cp.async double-buffer.
// 69.6 KB smem -> 3 blocks/SM; grid = 256 over all batches.
// 8 warps share the m16 tile; warp w covers n columns [16w, 16w+16).
// FC W/bias/window UNION into the stage region after the MMA loop.
// ---------------------------------------------------------------------------
__global__ void band_kernel(const float* __restrict__ fcw,
                            const float* __restrict__ fcb,
                            float* __restrict__ out) {
    extern __shared__ __align__(16) float sm[];   // SMEM_FLOATS

    const int blk = blockIdx.x;               // 0..255
    const int b = blk >> 6;                   // batch
    const int tb = (blk & 63) * BTILE;        // 0..1008
    const int j0 = tb - 56;
    const int tid = threadIdx.x;              // 256
    const int lane = tid & 31, warp = tid >> 5;

    const float* hb = g_hist + (size_t)b * (TT_TOT * NBINS);

    float acc[2][4];
#pragma unroll
    for (int nt = 0; nt < 2; nt++)
#pragma unroll
        for (int i = 0; i < 4; i++) acc[nt][i] = 0.f;

    // ---- stage loader: 128 rows x 16 float4 = 2048 cp.asyncs, 8 per thread.
    const int lrow0 = tid >> 4;
    const int lc4 = tid & 15;
    unsigned sbase = (unsigned)__cvta_generic_to_shared(sm);

    const float* lsrc[8];
    int lsz[8];
    unsigned ldst[8];
#pragma unroll
    for (int it = 0; it < 8; ++it) {
        int row = lrow0 + it * 16;
        int j = j0 + row;
        int jc = j < 0 ? 0 : (j > 1023 ? 1023 : j);
        lsrc[it] = hb + (size_t)jc * NBINS + lc4 * 4;
        lsz[it] = ((unsigned)j < 1024u) ? 16 : 0;
        ldst[it] = sbase + (unsigned)(row * SSTRIDE + lc4 * 4) * 4u;
    }

#define LOAD_STAGE(s, buf)                                                        \
    {                                                                             \
        const int kb = (s) * KCH;                                                 \
        const unsigned boff = (buf) * (STAGE_WORDS * 4u);                         \
        _Pragma("unroll")                                                         \
        for (int it = 0; it < 8; ++it) {                                          \
            asm volatile("cp.async.cg.shared.global [%0], [%1], 16, %2;\n"        \
                         :: "r"(ldst[it] + boff), "l"(lsrc[it] + kb),             \
                            "r"(lsz[it]));                                        \
        }                                                                         \
        asm volatile("cp.async.commit_group;\n");                                 \
    }

    LOAD_STAGE(0, 0)

    for (int s = 0; s < NSTAGES; ++s) {
        if (s < NSTAGES - 1) LOAD_STAGE(s + 1, (s + 1) & 1)
        asm volatile("cp.async.wait_group 1;\n" ::: "memory");
        __syncthreads();

        const float* B = sm + (s & 1) * STAGE_WORDS;
        const float* Ab = B + (56 + (lane >> 2)) * SSTRIDE + (lane & 3);
        const float* Bb = B + (warp * 16 + (lane >> 2)) * SSTRIDE + (lane & 3);

#pragma unroll
        for (int k8 = 0; k8 < KCH / 8; ++k8) {
            const int ko = k8 * 8;
            unsigned a0 = __float_as_uint(Ab[ko]);
            unsigned a1 = __float_as_uint(Ab[8 * SSTRIDE + ko]);
            unsigned a2 = __float_as_uint(Ab[ko + 4]);
            unsigned a3 = __float_as_uint(Ab[8 * SSTRIDE + ko + 4]);
#pragma unroll
            for (int nt = 0; nt < 2; ++nt) {
                unsigned b0 = __float_as_uint(Bb[nt * 8 * SSTRIDE + ko]);
                unsigned b1 = __float_as_uint(Bb[nt * 8 * SSTRIDE + ko + 4]);
                asm volatile(
                    "mma.sync.aligned.m16n8k8.row.col.f32.tf32.tf32.f32 "
                    "{%0,%1,%2,%3}, {%4,%5,%6,%7}, {%8,%9}, {%0,%1,%2,%3};\n"
                    : "+f"(acc[nt][0]), "+f"(acc[nt][1]),
                      "+f"(acc[nt][2]), "+f"(acc[nt][3])
                    : "r"(a0), "r"(a1), "r"(a2), "r"(a3), "r"(b0), "r"(b1));
            }
        }
        __syncthreads();
    }
    // All stage-buffer reads done; smem region is now reused for FC data.

    // ---- epilogue 1: scatter D(tr, jr) -> swin[tr][l], l = jr - tr - 6.
    {
        float* swin = sm + SWIN_OFF;
        const int tr0 = lane >> 2;
#pragma unroll
        for (int nt = 0; nt < 2; ++nt) {
            int jr = warp * 16 + nt * 8 + 2 * (lane & 3);
#pragma unroll
            for (int half = 0; half < 2; ++half) {
                int tr = tr0 + half * 8;
                int l = jr - tr - 6;
                if ((unsigned)l < (unsigned)LOOKUP)
                    swin[tr * WINP + l] = acc[nt][2 * half];
                if ((unsigned)(l + 1) < (unsigned)LOOKUP)
                    swin[tr * WINP + l + 1] = acc[nt][2 * half + 1];
            }
        }
    }

    // stage FC weights/bias into the freed stage region (disjoint from swin)
    {
        const float4* w4 = (const float4*)fcw;
        float4* sw4 = (float4*)(sm + SW_OFF);
        for (int e = tid; e < (LOOKUP * OUT_DIM) / 4; e += 256) sw4[e] = w4[e];
        if (tid < OUT_DIM) sm[SB_OFF + tid] = fcb[tid];
    }
    __syncthreads();

    // ---- epilogue 2: fused FC. Warp w -> t rows {2w, 2w+1}; lane -> 4 cols.
    {
        const float* sW = sm + SW_OFF;
        const float* swin = sm + SWIN_OFF;
        float4 bias = *(const float4*)(sm + SB_OFF + 4 * lane);

        float f[2][4];
#pragma unroll
        for (int r = 0; r < 2; ++r) {
            f[r][0] = bias.x; f[r][1] = bias.y; f[r][2] = bias.z; f[r][3] = bias.w;
        }

#pragma unroll 4
        for (int l = 0; l < LOOKUP; ++l) {
            float4 wv = *(const float4*)(sW + l * OUT_DIM + 4 * lane);
#pragma unroll
            for (int r = 0; r < 2; ++r) {
                float sv = swin[(2 * warp + r) * WINP + l];
                f[r][0] += sv * wv.x;
                f[r][1] += sv * wv.y;
                f[r][2] += sv * wv.z;
                f[r][3] += sv * wv.w;
            }
        }

#pragma unroll
        for (int r = 0; r < 2; ++r) {
            int t = tb + 2 * warp + r;
            float4 o;
            o.x = fmaxf(f[r][0], 0.f);
            o.y = fmaxf(f[r][1], 0.f);
            o.z = fmaxf(f[r][2], 0.f);
            o.w = fmaxf(f[r][3], 0.f);
            *(float4*)(out + ((size_t)(b * TT_TOT + t)) * OUT_DIM + 4 * lane) = o;
        }
    }
}

// ---------------------------------------------------------------------------
extern "C" void kernel_launch(void* const* d_in, const int* in_sizes, int n_in,
                              void* d_out, int out_size) {
    const int* frames = (const int*)d_in[0];
    const float* fcw = (const float*)d_in[1];
    const float* fcb = (const float*)d_in[2];
    float* out = (float*)d_out;

    cudaFuncSetAttribute(band_kernel, cudaFuncAttributeMaxDynamicSharedMemorySize,
                         SMEM_FLOATS * (int)sizeof(float));

    hist_kernel<<<BB * TT_TOT, 256>>>(frames);
    band_kernel<<<(BB * TT_TOT) / BTILE, 256, SMEM_FLOATS * sizeof(float)>>>(fcw, fcb, out);
}